// round 11
// baseline (speedup 1.0000x reference)
#include <cuda_runtime.h>
#include <cuda_fp16.h>
#include <cstdint>
#include <math.h>

#define BB 4
#define SQ 2048
#define SK 2048
#define DD 1024
#define HH 16
#define HDIM 64

// ---------------------------------------------------------------------------
// Static device scratch (no allocations anywhere)
// ---------------------------------------------------------------------------
__device__ __half g_xh[(size_t)BB * SQ * DD];   // hidden_states fp16
__device__ __half g_eh[(size_t)BB * SK * DD];   // encoder fp16
__device__ __half g_wq[(size_t)DD * DD];        // weights fp16
__device__ __half g_wk[(size_t)DD * DD];
__device__ __half g_wv[(size_t)DD * DD];

// projected Q/K/V in [B,H,S,HD] layout, fp16 (Q pre-scaled by 0.125*log2e)
__device__ __half g_qh[(size_t)BB * HH * SQ * HDIM];
__device__ __half g_kh[(size_t)BB * HH * SK * HDIM];
__device__ __half g_vh[(size_t)BB * HH * SK * HDIM];

// ---------------------------------------------------------------------------
// PTX helpers (baseline sm_80+ features only — harness targets plain sm_103)
// ---------------------------------------------------------------------------
__device__ __forceinline__ uint32_t smem_u32(const void* p) {
    uint32_t a;
    asm("{ .reg .u64 t; cvta.to.shared.u64 t, %1; cvt.u32.u64 %0, t; }"
        : "=r"(a) : "l"(p));
    return a;
}

__device__ __forceinline__ void cpa16(uint32_t s, const void* g) {
    asm volatile("cp.async.ca.shared.global [%0], [%1], 16;" :: "r"(s), "l"(g));
}
#define CP_COMMIT() asm volatile("cp.async.commit_group;" ::: "memory")
#define CP_WAIT(n)  asm volatile("cp.async.wait_group %0;" :: "n"(n) : "memory")

__device__ __forceinline__ void ldsm_x4(uint32_t* r, uint32_t addr) {
    asm volatile("ldmatrix.sync.aligned.m8n8.x4.shared.b16 {%0,%1,%2,%3}, [%4];"
                 : "=r"(r[0]), "=r"(r[1]), "=r"(r[2]), "=r"(r[3]) : "r"(addr));
}
__device__ __forceinline__ void ldsm_x4_t(uint32_t* r, uint32_t addr) {
    asm volatile("ldmatrix.sync.aligned.m8n8.x4.trans.shared.b16 {%0,%1,%2,%3}, [%4];"
                 : "=r"(r[0]), "=r"(r[1]), "=r"(r[2]), "=r"(r[3]) : "r"(addr));
}

// fp16 MMA, fp32 accumulate
__device__ __forceinline__ void mma16816h(float* c, const uint32_t* a,
                                          const uint32_t* b) {
    asm volatile(
        "mma.sync.aligned.m16n8k16.row.col.f32.f16.f16.f32 "
        "{%0,%1,%2,%3}, {%4,%5,%6,%7}, {%8,%9}, {%0,%1,%2,%3};"
        : "+f"(c[0]), "+f"(c[1]), "+f"(c[2]), "+f"(c[3])
        : "r"(a[0]), "r"(a[1]), "r"(a[2]), "r"(a[3]), "r"(b[0]), "r"(b[1]));
}

__device__ __forceinline__ float ex2f(float x) {
    float y;
    asm("ex2.approx.ftz.f32 %0, %1;" : "=f"(y) : "f"(x));
    return y;
}

// pack two fp32 into f16x2 (lo = a, hi = b)
__device__ __forceinline__ uint32_t pack_h2(float a, float b) {
    uint32_t r;
    asm("cvt.rn.f16x2.f32 %0, %1, %2;" : "=r"(r) : "f"(b), "f"(a));
    return r;
}

// swizzled byte offset: 128B rows, SW128 (bits[6:4] ^= row&7)
#define ASW(row, colb) \
    ((uint32_t)(((row) << 7) + ((colb) ^ ((((uint32_t)(row)) & 7u) << 4))))

// ---------------------------------------------------------------------------
// Fused fp32 -> fp16 convert of all five inputs (one launch)
// ---------------------------------------------------------------------------
#define NA4 ((BB * SQ * DD) / 4)   // 2097152
#define NW4 ((DD * DD) / 4)        // 262144
#define NCONV (2 * NA4 + 3 * NW4)  // 4980736

__global__ void convall_kernel(const float* __restrict__ hs,
                               const float* __restrict__ ehs,
                               const float* __restrict__ Wq,
                               const float* __restrict__ Wk,
                               const float* __restrict__ Wv) {
    int i = blockIdx.x * blockDim.x + threadIdx.x;
    if (i >= NCONV) return;
    const float* src;
    __half* dst;
    int j = i;
    if (j < NA4) {
        src = hs;  dst = g_xh;
    } else if ((j -= NA4) < NA4) {
        src = ehs; dst = g_eh;
    } else if ((j -= NA4) < NW4) {
        src = Wq;  dst = g_wq;
    } else if ((j -= NW4) < NW4) {
        src = Wk;  dst = g_wk;
    } else {
        j -= NW4;
        src = Wv;  dst = g_wv;
    }
    float4 v = ((const float4*)src)[j];
    ((uint2*)dst)[j] = make_uint2(pack_h2(v.x, v.y), pack_h2(v.z, v.w));
}

// ---------------------------------------------------------------------------
// Fused projection GEMM (fp16 HMMA): blockIdx.z = 0/1/2 -> Q/K/V.
// Block 128x128, BK=32, 256 thr (8 warps: 2m x 4n, warp tile 64x32).
// 3-stage smem ring, prefetch distance 2, one __syncthreads per k-tile.
// ---------------------------------------------------------------------------
#define PARR 10240u     // bytes per smem array (128 rows * 80B stride)
#define PBUF 20480u     // bytes per buffer (2 arrays: X, W)

__global__ __launch_bounds__(256, 2) void proj_tc() {
    extern __shared__ char smc[];
    const uint32_t smb = smem_u32(smc);
    const int tid = threadIdx.x;
    const int wid = tid >> 5, lane = tid & 31;
    const int gid = lane >> 2, tig = lane & 3;
    const int wm = wid & 1, wn = wid >> 1;
    const int n0 = blockIdx.x * 128;
    const int m0 = blockIdx.y * 128;
    const int which = blockIdx.z;

    const __half* x = (which == 0) ? g_xh : g_eh;
    const __half* w = (which == 0) ? g_wq : (which == 1) ? g_wk : g_wv;

    float acc[4][4][4];
#pragma unroll
    for (int a = 0; a < 4; a++)
#pragma unroll
        for (int bq = 0; bq < 4; bq++)
#pragma unroll
            for (int c = 0; c < 4; c++) acc[a][bq][c] = 0.0f;

    // loader: 2 arrays * 128 rows * 4 segs(16B) = 1024 chunks / 256 thr = 4
    auto load_tile = [&](int kc, int p) {
        const int k0 = kc * 32;
        const uint32_t base = smb + (uint32_t)p * PBUF;
#pragma unroll
        for (int i = 0; i < 4; i++) {
            int c = tid + i * 256;
            int arr = c >> 9;
            int row = (c >> 2) & 127;
            int seg = c & 3;
            const __half* g = arr ? (w + (size_t)(n0 + row) * DD + k0 + seg * 8)
                                  : (x + (size_t)(m0 + row) * DD + k0 + seg * 8);
            cpa16(base + arr * PARR + row * 80 + seg * 16, g);
        }
        CP_COMMIT();
    };

    const int rowA = lane & 15, colA = (lane >> 4) * 8;
    const int rowB = (lane & 7) + ((lane >> 4) << 3);
    const int colB = ((lane >> 3) & 1) * 8;

    load_tile(0, 0);
    load_tile(1, 1);
    for (int t = 0; t < 32; t++) {
        if (t + 1 < 32) {
            CP_WAIT(1);   // tile t landed; t+1 may be in flight
        } else {
            CP_WAIT(0);
        }
        __syncthreads();
        if (t + 2 < 32) load_tile(t + 2, (t + 2) % 3);

        const uint32_t bbase = smb + (uint32_t)(t % 3) * PBUF;
        const uint32_t X_s = bbase;
        const uint32_t W_s = bbase + PARR;

#pragma unroll
        for (int ks = 0; ks < 2; ks++) {
            const int k0s = ks * 16;
            uint32_t bw[2][4];
#pragma unroll
            for (int np = 0; np < 2; np++) {
                uint32_t ad = (wn * 32 + np * 16 + rowB) * 80 + (k0s + colB) * 2;
                ldsm_x4(bw[np], W_s + ad);
            }
#pragma unroll
            for (int mt = 0; mt < 4; mt++) {
                uint32_t ah[4];
                uint32_t ad = (wm * 64 + mt * 16 + rowA) * 80 + (k0s + colA) * 2;
                ldsm_x4(ah, X_s + ad);
#pragma unroll
                for (int nt = 0; nt < 4; nt++) {
                    const uint32_t* bp = &bw[nt >> 1][(nt & 1) * 2];
                    mma16816h(acc[mt][nt], ah, bp);
                }
            }
        }
    }

    // epilogue: fp16 write into head layout
    __half* dh = (which == 0) ? g_qh : (which == 1) ? g_kh : g_vh;
    const float qs = (which == 0) ? (0.125f * 1.4426950408889634f) : 1.0f;

#pragma unroll
    for (int mt = 0; mt < 4; mt++) {
        int m = m0 + wm * 64 + mt * 16 + gid;
        int bb = m >> 11;
        int s = m & (SQ - 1);
#pragma unroll
        for (int nt = 0; nt < 4; nt++) {
            int n = n0 + wn * 32 + nt * 8 + 2 * tig;
            int head = n >> 6;
            int hd = n & 63;
            size_t idx = (((size_t)bb * HH + head) * SQ + s) * HDIM + hd;
            *(uint32_t*)(dh + idx) =
                pack_h2(acc[mt][nt][0] * qs, acc[mt][nt][1] * qs);
            *(uint32_t*)(dh + idx + 8 * HDIM) =
                pack_h2(acc[mt][nt][2] * qs, acc[mt][nt][3] * qs);
        }
    }
}

// ---------------------------------------------------------------------------
// Flash attention (fp16 HMMA), software-pipelined with CORRECT cp.async
// fencing: per iter t -> softmax(S_t) [QK(t) issued last iter], pack P,
// load_kv(t+2)+CP_WAIT, __syncthreads (cross-thread visibility of tile t+1),
// then issue QK(t+1) and PV(t) back-to-back. Each warp enters the next
// softmax with 64 MMAs queued. 4-slot KV ring, one barrier per tile.
// Block = 128 q, 8 warps, warp = 16 q x 64 keys.
// ---------------------------------------------------------------------------
#define QARR 16384u    // 128 rows * 128B
#define KARR 8192u     // 64 rows * 128B
#define KVBUF 16384u   // 2 arrays (K, V) per slot

__global__ __launch_bounds__(256) void attn_tc(float* __restrict__ out) {
    extern __shared__ char smc[];
    const uint32_t smb = smem_u32(smc);
    const int tid = threadIdx.x;
    const int wid = tid >> 5, lane = tid & 31;
    const int gid = lane >> 2, tig = lane & 3;
    const int q0 = blockIdx.x * 128;
    const int h = blockIdx.y, b = blockIdx.z;

    const size_t bh = (size_t)b * HH + h;
    const __half* Qh_g = g_qh + (bh * SQ + q0) * HDIM;
    const __half* Kh_g = g_kh + bh * SK * HDIM;
    const __half* Vh_g = g_vh + bh * SK * HDIM;

    const uint32_t QH = smb;
    const uint32_t KV = smb + QARR;   // 4 slots

    // Q load: 128 rows * 8 segs = 1024 chunks / 256 thr = 4 each
#pragma unroll
    for (int i = 0; i < 4; i++) {
        int c = tid + i * 256;
        int row = (c >> 3) & 127;
        int seg = c & 7;
        cpa16(QH + ASW(row, seg * 16), Qh_g + row * HDIM + seg * 8);
    }
    CP_COMMIT();

    // KV load: 2 arrays * 64 rows * 8 segs = 1024 chunks / 256 thr = 4 each
    auto load_kv = [&](int kt, int p) {
        const uint32_t base = KV + (uint32_t)p * KVBUF;
        const int key0 = kt * 64;
#pragma unroll
        for (int i = 0; i < 4; i++) {
            int c = tid + i * 256;
            int arr = c >> 9;
            int row = (c >> 3) & 63;
            int seg = c & 7;
            const __half* g =
                (arr ? Vh_g : Kh_g) + (size_t)(key0 + row) * HDIM + seg * 8;
            cpa16(base + arr * KARR + ASW(row, seg * 16), g);
        }
        CP_COMMIT();
    };

    load_kv(0, 0);
    load_kv(1, 1);
    CP_WAIT(0);        // Q + kv0 + kv1 all landed (own thread)
    __syncthreads();   // ... and visible to all threads

    // preload Q fragments
    const int rowA = lane & 15;
    const int colAb = (lane >> 4) * 16;
    uint32_t qh[4][4];
#pragma unroll
    for (int kk = 0; kk < 4; kk++)
        ldsm_x4(qh[kk], QH + ASW(wid * 16 + rowA, kk * 32 + colAb));

    const int rowB = (lane & 7) + ((lane >> 4) << 3);
    const int colBb = ((lane >> 3) & 1) * 16;
    const int rowV = (lane & 7) + (((lane >> 3) & 1) << 3);
    const int colVb = (lane >> 4) * 16;

    float s[8][4];
    float ctx[8][4];
#pragma unroll
    for (int t = 0; t < 8; t++)
#pragma unroll
        for (int c = 0; c < 4; c++) ctx[t][c] = 0.0f;
    float m_a = -1e30f, m_b = -1e30f, l_a = 0.0f, l_b = 0.0f;  // l per-lane

    // issue QK for a tile into s (zeroes s first)
    auto qk_tile = [&](int kt) {
        const uint32_t KHs = KV + (uint32_t)(kt & 3) * KVBUF;
#pragma unroll
        for (int tt = 0; tt < 8; tt++)
#pragma unroll
            for (int c = 0; c < 4; c++) s[tt][c] = 0.0f;
#pragma unroll
        for (int kk = 0; kk < 4; kk++) {
#pragma unroll
            for (int nn = 0; nn < 4; nn++) {
                uint32_t kh4[4];
                ldsm_x4(kh4, KHs + ASW(nn * 16 + rowB, kk * 32 + colBb));
                mma16816h(s[2 * nn], qh[kk], kh4);
                mma16816h(s[2 * nn + 1], qh[kk], kh4 + 2);
            }
        }
    };

    const int NT = SK / 64;
    qk_tile(0);   // S_0 in flight

    for (int t = 0; t < NT; t++) {
        // ---- softmax on S_t (producing mma issued at iter t-1) ----
        float mA = s[0][0], mB = s[0][2];
#pragma unroll
        for (int tt = 0; tt < 8; tt++) {
            mA = fmaxf(mA, fmaxf(s[tt][0], s[tt][1]));
            mB = fmaxf(mB, fmaxf(s[tt][2], s[tt][3]));
        }
        mA = fmaxf(mA, __shfl_xor_sync(0xffffffffu, mA, 1));
        mA = fmaxf(mA, __shfl_xor_sync(0xffffffffu, mA, 2));
        mB = fmaxf(mB, __shfl_xor_sync(0xffffffffu, mB, 1));
        mB = fmaxf(mB, __shfl_xor_sync(0xffffffffu, mB, 2));
        float nmA = fmaxf(m_a, mA), nmB = fmaxf(m_b, mB);
        float corrA = ex2f(m_a - nmA), corrB = ex2f(m_b - nmB);

        float rA = 0.0f, rB = 0.0f;
#pragma unroll
        for (int tt = 0; tt < 8; tt++) {
            s[tt][0] = ex2f(s[tt][0] - nmA);
            s[tt][1] = ex2f(s[tt][1] - nmA);
            s[tt][2] = ex2f(s[tt][2] - nmB);
            s[tt][3] = ex2f(s[tt][3] - nmB);
            rA += s[tt][0] + s[tt][1];
            rB += s[tt][2] + s[tt][3];
        }
        l_a = l_a * corrA + rA;   // per-lane partial; reduced after loop
        l_b = l_b * corrB + rB;
        m_a = nmA;
        m_b = nmB;
#pragma unroll
        for (int tt = 0; tt < 8; tt++) {
            ctx[tt][0] *= corrA;
            ctx[tt][1] *= corrA;
            ctx[tt][2] *= corrB;
            ctx[tt][3] *= corrB;
        }

        // pack P (S_t now dead -> registers reusable by QK(t+1))
        uint32_t ah16[16];
#pragma unroll
        for (int j = 0; j < 4; j++) {
            ah16[j * 4 + 0] = pack_h2(s[2 * j][0], s[2 * j][1]);
            ah16[j * 4 + 1] = pack_h2(s[2 * j][2], s[2 * j][3]);
            ah16[j * 4 + 2] = pack_h2(s[2 * j + 1][0], s[2 * j + 1][1]);
            ah16[j * 4 + 3] = pack_h2(s[2 * j + 1][2], s[2 * j + 1][3]);
        }

        // ---- prefetch + fence: ensure tile t+1 fully visible CTA-wide ----
        if (t + 2 < NT) {
            load_kv(t + 2, (t + 2) & 3);   // pending: kv(t+1), kv(t+2)
            CP_WAIT(1);                    // kv(t+1) landed (own thread)
        } else {
            CP_WAIT(0);                    // drain everything at the tail
        }
        __syncthreads();                   // cross-thread visibility

        // ---- queue QK(t+1), then PV(t): 64 mma cover next softmax ----
        if (t + 1 < NT) qk_tile(t + 1);

        const uint32_t VHs = KV + (uint32_t)(t & 3) * KVBUF + KARR;
#pragma unroll
        for (int j = 0; j < 4; j++) {
#pragma unroll
            for (int hp = 0; hp < 4; hp++) {
                uint32_t vh4[4];
                ldsm_x4_t(vh4, VHs + ASW(j * 16 + rowV, hp * 32 + colVb));
                mma16816h(ctx[2 * hp], &ah16[j * 4], vh4);
                mma16816h(ctx[2 * hp + 1], &ah16[j * 4], vh4 + 2);
            }
        }
    }

    // final cross-lane reduction of l (deferred from the loop)
    l_a += __shfl_xor_sync(0xffffffffu, l_a, 1);
    l_a += __shfl_xor_sync(0xffffffffu, l_a, 2);
    l_b += __shfl_xor_sync(0xffffffffu, l_b, 1);
    l_b += __shfl_xor_sync(0xffffffffu, l_b, 2);

    // epilogue
    float invA = 1.0f / l_a, invB = 1.0f / l_b;
    int qA = q0 + wid * 16 + gid;
    float* oA = out + ((size_t)b * SQ + qA) * DD + h * HDIM;
    float* oB = oA + (size_t)8 * DD;
#pragma unroll
    for (int tt = 0; tt < 8; tt++) {
        int hd = 8 * tt + 2 * tig;
        float2 a2 = make_float2(ctx[tt][0] * invA, ctx[tt][1] * invA);
        float2 b2 = make_float2(ctx[tt][2] * invB, ctx[tt][3] * invB);
        *(float2*)(oA + hd) = a2;
        *(float2*)(oB + hd) = b2;
    }
}

// ---------------------------------------------------------------------------
extern "C" void kernel_launch(void* const* d_in, const int* in_sizes, int n_in,
                              void* d_out, int out_size) {
    const float* hs = (const float*)d_in[0];
    const float* ehs = (const float*)d_in[1];
    const float* Wq = (const float*)d_in[2];
    const float* Wk = (const float*)d_in[3];
    const float* Wv = (const float*)d_in[4];
    float* out = (float*)d_out;

    // single fused convert launch
    convall_kernel<<<(NCONV + 255) / 256, 256>>>(hs, ehs, Wq, Wk, Wv);

    // single fused projection launch (Q, K, V via blockIdx.z)
    {
        size_t smem = 3 * PBUF;  // 61440
        cudaFuncSetAttribute(proj_tc, cudaFuncAttributeMaxDynamicSharedMemorySize,
                             (int)smem);
        dim3 grid(DD / 128, (BB * SQ) / 128, 3);
        proj_tc<<<grid, 256, smem>>>();
    }

    // attention (4-slot KV ring)
    {
        size_t smem = QARR + 4 * KVBUF;  // 81920
        cudaFuncSetAttribute(attn_tc, cudaFuncAttributeMaxDynamicSharedMemorySize,
                             (int)smem);
        attn_tc<<<dim3(SQ / 128, HH, BB), 256, smem>>>(out);
    }
}

// round 12
// speedup vs baseline: 1.1216x; 1.1216x over previous
#include <cuda_runtime.h>
#include <cuda_fp16.h>
#include <cstdint>
#include <math.h>

#define BB 4
#define SQ 2048
#define SK 2048
#define DD 1024
#define HH 16
#define HDIM 64

// ---------------------------------------------------------------------------
// Static device scratch (no allocations anywhere)
// ---------------------------------------------------------------------------
__device__ __half g_xh[(size_t)BB * SQ * DD];   // hidden_states fp16
__device__ __half g_eh[(size_t)BB * SK * DD];   // encoder fp16
__device__ __half g_wq[(size_t)DD * DD];        // weights fp16
__device__ __half g_wk[(size_t)DD * DD];
__device__ __half g_wv[(size_t)DD * DD];

// projected Q/K/V in [B,H,S,HD] layout, fp16 (Q pre-scaled by 0.125*log2e)
__device__ __half g_qh[(size_t)BB * HH * SQ * HDIM];
__device__ __half g_kh[(size_t)BB * HH * SK * HDIM];
__device__ __half g_vh[(size_t)BB * HH * SK * HDIM];

// ---------------------------------------------------------------------------
// PTX helpers (baseline sm_80+ features only — harness targets plain sm_103)
// ---------------------------------------------------------------------------
__device__ __forceinline__ uint32_t smem_u32(const void* p) {
    uint32_t a;
    asm("{ .reg .u64 t; cvta.to.shared.u64 t, %1; cvt.u32.u64 %0, t; }"
        : "=r"(a) : "l"(p));
    return a;
}

__device__ __forceinline__ void cpa16(uint32_t s, const void* g) {
    asm volatile("cp.async.ca.shared.global [%0], [%1], 16;" :: "r"(s), "l"(g));
}
#define CP_COMMIT() asm volatile("cp.async.commit_group;" ::: "memory")
#define CP_WAIT(n)  asm volatile("cp.async.wait_group %0;" :: "n"(n) : "memory")

__device__ __forceinline__ void ldsm_x4(uint32_t* r, uint32_t addr) {
    asm volatile("ldmatrix.sync.aligned.m8n8.x4.shared.b16 {%0,%1,%2,%3}, [%4];"
                 : "=r"(r[0]), "=r"(r[1]), "=r"(r[2]), "=r"(r[3]) : "r"(addr));
}
__device__ __forceinline__ void ldsm_x4_t(uint32_t* r, uint32_t addr) {
    asm volatile("ldmatrix.sync.aligned.m8n8.x4.trans.shared.b16 {%0,%1,%2,%3}, [%4];"
                 : "=r"(r[0]), "=r"(r[1]), "=r"(r[2]), "=r"(r[3]) : "r"(addr));
}

// fp16 MMA, fp32 accumulate
__device__ __forceinline__ void mma16816h(float* c, const uint32_t* a,
                                          const uint32_t* b) {
    asm volatile(
        "mma.sync.aligned.m16n8k16.row.col.f32.f16.f16.f32 "
        "{%0,%1,%2,%3}, {%4,%5,%6,%7}, {%8,%9}, {%0,%1,%2,%3};"
        : "+f"(c[0]), "+f"(c[1]), "+f"(c[2]), "+f"(c[3])
        : "r"(a[0]), "r"(a[1]), "r"(a[2]), "r"(a[3]), "r"(b[0]), "r"(b[1]));
}

__device__ __forceinline__ float ex2f(float x) {
    float y;
    asm("ex2.approx.ftz.f32 %0, %1;" : "=f"(y) : "f"(x));
    return y;
}

// pack two fp32 into f16x2 (lo = a, hi = b)
__device__ __forceinline__ uint32_t pack_h2(float a, float b) {
    uint32_t r;
    asm("cvt.rn.f16x2.f32 %0, %1, %2;" : "=r"(r) : "f"(b), "f"(a));
    return r;
}

// swizzled byte offset: 128B rows, SW128 (bits[6:4] ^= row&7)
#define ASW(row, colb) \
    ((uint32_t)(((row) << 7) + ((colb) ^ ((((uint32_t)(row)) & 7u) << 4))))

// ---------------------------------------------------------------------------
// Fused fp32 -> fp16 convert of all five inputs (one launch, 8 floats/thread)
// ---------------------------------------------------------------------------
#define NA8 ((BB * SQ * DD) / 8)   // 1048576
#define NW8 ((DD * DD) / 8)        // 131072
#define NCONV8 (2 * NA8 + 3 * NW8) // 2490368

__global__ void convall_kernel(const float* __restrict__ hs,
                               const float* __restrict__ ehs,
                               const float* __restrict__ Wq,
                               const float* __restrict__ Wk,
                               const float* __restrict__ Wv) {
    int i = blockIdx.x * blockDim.x + threadIdx.x;
    if (i >= NCONV8) return;
    const float* src;
    __half* dst;
    int j = i;
    if (j < NA8) {
        src = hs;  dst = g_xh;
    } else if ((j -= NA8) < NA8) {
        src = ehs; dst = g_eh;
    } else if ((j -= NA8) < NW8) {
        src = Wq;  dst = g_wq;
    } else if ((j -= NW8) < NW8) {
        src = Wk;  dst = g_wk;
    } else {
        j -= NW8;
        src = Wv;  dst = g_wv;
    }
    float4 v0 = ((const float4*)src)[j * 2 + 0];
    float4 v1 = ((const float4*)src)[j * 2 + 1];
    uint4 o;
    o.x = pack_h2(v0.x, v0.y);
    o.y = pack_h2(v0.z, v0.w);
    o.z = pack_h2(v1.x, v1.y);
    o.w = pack_h2(v1.z, v1.w);
    ((uint4*)dst)[j] = o;
}

// ---------------------------------------------------------------------------
// Fused projection GEMM (fp16 HMMA): blockIdx.z = 0/1/2 -> Q/K/V.
// Block 128x128, BK=32, 256 thr (8 warps: 2m x 4n, warp tile 64x32).
// 3-stage smem ring, prefetch distance 2, one __syncthreads per k-tile.
// (unchanged from round 9)
// ---------------------------------------------------------------------------
#define PARR 10240u     // bytes per smem array (128 rows * 80B stride)
#define PBUF 20480u     // bytes per buffer (2 arrays: X, W)

__global__ __launch_bounds__(256, 2) void proj_tc() {
    extern __shared__ char smc[];
    const uint32_t smb = smem_u32(smc);
    const int tid = threadIdx.x;
    const int wid = tid >> 5, lane = tid & 31;
    const int gid = lane >> 2, tig = lane & 3;
    const int wm = wid & 1, wn = wid >> 1;
    const int n0 = blockIdx.x * 128;
    const int m0 = blockIdx.y * 128;
    const int which = blockIdx.z;

    const __half* x = (which == 0) ? g_xh : g_eh;
    const __half* w = (which == 0) ? g_wq : (which == 1) ? g_wk : g_wv;

    float acc[4][4][4];
#pragma unroll
    for (int a = 0; a < 4; a++)
#pragma unroll
        for (int bq = 0; bq < 4; bq++)
#pragma unroll
            for (int c = 0; c < 4; c++) acc[a][bq][c] = 0.0f;

    // loader: 2 arrays * 128 rows * 4 segs(16B) = 1024 chunks / 256 thr = 4
    auto load_tile = [&](int kc, int p) {
        const int k0 = kc * 32;
        const uint32_t base = smb + (uint32_t)p * PBUF;
#pragma unroll
        for (int i = 0; i < 4; i++) {
            int c = tid + i * 256;
            int arr = c >> 9;
            int row = (c >> 2) & 127;
            int seg = c & 3;
            const __half* g = arr ? (w + (size_t)(n0 + row) * DD + k0 + seg * 8)
                                  : (x + (size_t)(m0 + row) * DD + k0 + seg * 8);
            cpa16(base + arr * PARR + row * 80 + seg * 16, g);
        }
        CP_COMMIT();
    };

    const int rowA = lane & 15, colA = (lane >> 4) * 8;
    const int rowB = (lane & 7) + ((lane >> 4) << 3);
    const int colB = ((lane >> 3) & 1) * 8;

    load_tile(0, 0);
    load_tile(1, 1);
    for (int t = 0; t < 32; t++) {
        if (t + 1 < 32) {
            CP_WAIT(1);   // tile t landed; t+1 may be in flight
        } else {
            CP_WAIT(0);
        }
        __syncthreads();
        if (t + 2 < 32) load_tile(t + 2, (t + 2) % 3);

        const uint32_t bbase = smb + (uint32_t)(t % 3) * PBUF;
        const uint32_t X_s = bbase;
        const uint32_t W_s = bbase + PARR;

#pragma unroll
        for (int ks = 0; ks < 2; ks++) {
            const int k0s = ks * 16;
            uint32_t bw[2][4];
#pragma unroll
            for (int np = 0; np < 2; np++) {
                uint32_t ad = (wn * 32 + np * 16 + rowB) * 80 + (k0s + colB) * 2;
                ldsm_x4(bw[np], W_s + ad);
            }
#pragma unroll
            for (int mt = 0; mt < 4; mt++) {
                uint32_t ah[4];
                uint32_t ad = (wm * 64 + mt * 16 + rowA) * 80 + (k0s + colA) * 2;
                ldsm_x4(ah, X_s + ad);
#pragma unroll
                for (int nt = 0; nt < 4; nt++) {
                    const uint32_t* bp = &bw[nt >> 1][(nt & 1) * 2];
                    mma16816h(acc[mt][nt], ah, bp);
                }
            }
        }
    }

    // epilogue: fp16 write into head layout
    __half* dh = (which == 0) ? g_qh : (which == 1) ? g_kh : g_vh;
    const float qs = (which == 0) ? (0.125f * 1.4426950408889634f) : 1.0f;

#pragma unroll
    for (int mt = 0; mt < 4; mt++) {
        int m = m0 + wm * 64 + mt * 16 + gid;
        int bb = m >> 11;
        int s = m & (SQ - 1);
#pragma unroll
        for (int nt = 0; nt < 4; nt++) {
            int n = n0 + wn * 32 + nt * 8 + 2 * tig;
            int head = n >> 6;
            int hd = n & 63;
            size_t idx = (((size_t)bb * HH + head) * SQ + s) * HDIM + hd;
            *(uint32_t*)(dh + idx) =
                pack_h2(acc[mt][nt][0] * qs, acc[mt][nt][1] * qs);
            *(uint32_t*)(dh + idx + 8 * HDIM) =
                pack_h2(acc[mt][nt][2] * qs, acc[mt][nt][3] * qs);
        }
    }
}

// ---------------------------------------------------------------------------
// Flash attention (fp16 HMMA) — round-9 schedule (cross-warp overlap at
// 2 CTAs/SM carries the softmax latency) + deferred cross-lane l reduction.
// Block = 128 q, 8 warps, warp = 16 q x 64 keys. 3-slot KV ring, prefetch
// distance 2, one __syncthreads per tile. smem 64KB/CTA.
// ---------------------------------------------------------------------------
#define QARR 16384u    // 128 rows * 128B
#define KARR 8192u     // 64 rows * 128B
#define KVBUF 16384u   // 2 arrays (K, V) per slot

__global__ __launch_bounds__(256, 2) void attn_tc(float* __restrict__ out) {
    extern __shared__ char smc[];
    const uint32_t smb = smem_u32(smc);
    const int tid = threadIdx.x;
    const int wid = tid >> 5, lane = tid & 31;
    const int gid = lane >> 2, tig = lane & 3;
    const int q0 = blockIdx.x * 128;
    const int h = blockIdx.y, b = blockIdx.z;

    const size_t bh = (size_t)b * HH + h;
    const __half* Qh_g = g_qh + (bh * SQ + q0) * HDIM;
    const __half* Kh_g = g_kh + bh * SK * HDIM;
    const __half* Vh_g = g_vh + bh * SK * HDIM;

    const uint32_t QH = smb;
    const uint32_t KV = smb + QARR;   // 3 slots

    // Q load: 128 rows * 8 segs = 1024 chunks / 256 thr = 4 each
#pragma unroll
    for (int i = 0; i < 4; i++) {
        int c = tid + i * 256;
        int row = (c >> 3) & 127;
        int seg = c & 7;
        cpa16(QH + ASW(row, seg * 16), Qh_g + row * HDIM + seg * 8);
    }
    CP_COMMIT();

    // KV load: 2 arrays * 64 rows * 8 segs = 1024 chunks / 256 thr = 4 each
    auto load_kv = [&](int kt, int p) {
        const uint32_t base = KV + (uint32_t)p * KVBUF;
        const int key0 = kt * 64;
#pragma unroll
        for (int i = 0; i < 4; i++) {
            int c = tid + i * 256;
            int arr = c >> 9;
            int row = (c >> 3) & 63;
            int seg = c & 7;
            const __half* g =
                (arr ? Vh_g : Kh_g) + (size_t)(key0 + row) * HDIM + seg * 8;
            cpa16(base + arr * KARR + ASW(row, seg * 16), g);
        }
        CP_COMMIT();
    };

    load_kv(0, 0);
    load_kv(1, 1);
    CP_WAIT(2);   // Q group complete; kv0/kv1 may be in flight
    __syncthreads();

    // preload Q fragments
    const int rowA = lane & 15;
    const int colAb = (lane >> 4) * 16;
    uint32_t qh[4][4];
#pragma unroll
    for (int kk = 0; kk < 4; kk++)
        ldsm_x4(qh[kk], QH + ASW(wid * 16 + rowA, kk * 32 + colAb));

    float ctx[8][4];
#pragma unroll
    for (int t = 0; t < 8; t++)
#pragma unroll
        for (int c = 0; c < 4; c++) ctx[t][c] = 0.0f;
    float m_a = -1e30f, m_b = -1e30f, l_a = 0.0f, l_b = 0.0f;  // l per-lane

    const int rowB = (lane & 7) + ((lane >> 4) << 3);
    const int colBb = ((lane >> 3) & 1) * 16;
    const int rowV = (lane & 7) + (((lane >> 3) & 1) << 3);
    const int colVb = (lane >> 4) * 16;

    const int NT = SK / 64;
    for (int t = 0; t < NT; t++) {
        if (t + 1 < NT) {
            CP_WAIT(1);   // tile t landed; t+1 in flight
        } else {
            CP_WAIT(0);
        }
        __syncthreads();
        if (t + 2 < NT) load_kv(t + 2, (t + 2) % 3);

        const uint32_t kb = KV + (uint32_t)(t % 3) * KVBUF;
        const uint32_t KHs = kb, VHs = kb + KARR;

        // S = Q K^T (single term)
        float s[8][4];
#pragma unroll
        for (int tt = 0; tt < 8; tt++)
#pragma unroll
            for (int c = 0; c < 4; c++) s[tt][c] = 0.0f;

#pragma unroll
        for (int kk = 0; kk < 4; kk++) {
#pragma unroll
            for (int nn = 0; nn < 4; nn++) {
                uint32_t kh4[4];
                ldsm_x4(kh4, KHs + ASW(nn * 16 + rowB, kk * 32 + colBb));
                mma16816h(s[2 * nn], qh[kk], kh4);
                mma16816h(s[2 * nn + 1], qh[kk], kh4 + 2);
            }
        }

        // online softmax (log2 domain via pre-scaled Q); l kept per-lane
        float mA = s[0][0], mB = s[0][2];
#pragma unroll
        for (int tt = 0; tt < 8; tt++) {
            mA = fmaxf(mA, fmaxf(s[tt][0], s[tt][1]));
            mB = fmaxf(mB, fmaxf(s[tt][2], s[tt][3]));
        }
        mA = fmaxf(mA, __shfl_xor_sync(0xffffffffu, mA, 1));
        mA = fmaxf(mA, __shfl_xor_sync(0xffffffffu, mA, 2));
        mB = fmaxf(mB, __shfl_xor_sync(0xffffffffu, mB, 1));
        mB = fmaxf(mB, __shfl_xor_sync(0xffffffffu, mB, 2));
        float nmA = fmaxf(m_a, mA), nmB = fmaxf(m_b, mB);
        float corrA = ex2f(m_a - nmA), corrB = ex2f(m_b - nmB);

        float rA = 0.0f, rB = 0.0f;
#pragma unroll
        for (int tt = 0; tt < 8; tt++) {
            s[tt][0] = ex2f(s[tt][0] - nmA);
            s[tt][1] = ex2f(s[tt][1] - nmA);
            s[tt][2] = ex2f(s[tt][2] - nmB);
            s[tt][3] = ex2f(s[tt][3] - nmB);
            rA += s[tt][0] + s[tt][1];
            rB += s[tt][2] + s[tt][3];
        }
        l_a = l_a * corrA + rA;   // per-lane partial; corr is quad-uniform
        l_b = l_b * corrB + rB;
        m_a = nmA;
        m_b = nmB;
#pragma unroll
        for (int tt = 0; tt < 8; tt++) {
            ctx[tt][0] *= corrA;
            ctx[tt][1] *= corrA;
            ctx[tt][2] *= corrB;
            ctx[tt][3] *= corrB;
        }

        // ctx += P V  (P fp16)
#pragma unroll
        for (int j = 0; j < 4; j++) {
            uint32_t ah[4];
            ah[0] = pack_h2(s[2 * j][0], s[2 * j][1]);
            ah[1] = pack_h2(s[2 * j][2], s[2 * j][3]);
            ah[2] = pack_h2(s[2 * j + 1][0], s[2 * j + 1][1]);
            ah[3] = pack_h2(s[2 * j + 1][2], s[2 * j + 1][3]);
#pragma unroll
            for (int hp = 0; hp < 4; hp++) {
                uint32_t vh4[4];
                ldsm_x4_t(vh4, VHs + ASW(j * 16 + rowV, hp * 32 + colVb));
                mma16816h(ctx[2 * hp], ah, vh4);
                mma16816h(ctx[2 * hp + 1], ah, vh4 + 2);
            }
        }
    }

    // deferred cross-lane reduction of l
    l_a += __shfl_xor_sync(0xffffffffu, l_a, 1);
    l_a += __shfl_xor_sync(0xffffffffu, l_a, 2);
    l_b += __shfl_xor_sync(0xffffffffu, l_b, 1);
    l_b += __shfl_xor_sync(0xffffffffu, l_b, 2);

    // epilogue
    float invA = 1.0f / l_a, invB = 1.0f / l_b;
    int qA = q0 + wid * 16 + gid;
    float* oA = out + ((size_t)b * SQ + qA) * DD + h * HDIM;
    float* oB = oA + (size_t)8 * DD;
#pragma unroll
    for (int tt = 0; tt < 8; tt++) {
        int hd = 8 * tt + 2 * tig;
        float2 a2 = make_float2(ctx[tt][0] * invA, ctx[tt][1] * invA);
        float2 b2 = make_float2(ctx[tt][2] * invB, ctx[tt][3] * invB);
        *(float2*)(oA + hd) = a2;
        *(float2*)(oB + hd) = b2;
    }
}

// ---------------------------------------------------------------------------
extern "C" void kernel_launch(void* const* d_in, const int* in_sizes, int n_in,
                              void* d_out, int out_size) {
    const float* hs = (const float*)d_in[0];
    const float* ehs = (const float*)d_in[1];
    const float* Wq = (const float*)d_in[2];
    const float* Wk = (const float*)d_in[3];
    const float* Wv = (const float*)d_in[4];
    float* out = (float*)d_out;

    // single fused convert launch (8 floats per thread)
    convall_kernel<<<(NCONV8 + 255) / 256, 256>>>(hs, ehs, Wq, Wk, Wv);

    // single fused projection launch (Q, K, V via blockIdx.z)
    {
        size_t smem = 3 * PBUF;  // 61440
        cudaFuncSetAttribute(proj_tc, cudaFuncAttributeMaxDynamicSharedMemorySize,
                             (int)smem);
        dim3 grid(DD / 128, (BB * SQ) / 128, 3);
        proj_tc<<<grid, 256, smem>>>();
    }

    // attention (3-slot KV ring, round-9 schedule)
    {
        size_t smem = QARR + 3 * KVBUF;  // 65536
        cudaFuncSetAttribute(attn_tc, cudaFuncAttributeMaxDynamicSharedMemorySize,
                             (int)smem);
        attn_tc<<<dim3(SQ / 128, HH, BB), 256, smem>>>(out);
    }
}

// round 13
// speedup vs baseline: 1.1828x; 1.0545x over previous
#include <cuda_runtime.h>
#include <cuda_fp16.h>
#include <cstdint>
#include <math.h>

#define BB 4
#define SQ 2048
#define SK 2048
#define DD 1024
#define HH 16
#define HDIM 64

// ---------------------------------------------------------------------------
// Static device scratch (no allocations anywhere)
// ---------------------------------------------------------------------------
__device__ __half g_xh[(size_t)BB * SQ * DD];   // hidden_states fp16
__device__ __half g_eh[(size_t)BB * SK * DD];   // encoder fp16
__device__ __half g_wq[(size_t)DD * DD];        // weights fp16
__device__ __half g_wk[(size_t)DD * DD];
__device__ __half g_wv[(size_t)DD * DD];

// projected Q/K/V in [B,H,S,HD] layout, fp16 (Q pre-scaled by 0.125*log2e)
__device__ __half g_qh[(size_t)BB * HH * SQ * HDIM];
__device__ __half g_kh[(size_t)BB * HH * SK * HDIM];
__device__ __half g_vh[(size_t)BB * HH * SK * HDIM];

// proj-completion counters: [which][batch], target 128 CTAs each
__device__ int g_cnt[12];

// ---------------------------------------------------------------------------
// PTX helpers (baseline sm_80+ features only — harness targets plain sm_103)
// ---------------------------------------------------------------------------
__device__ __forceinline__ uint32_t smem_u32(const void* p) {
    uint32_t a;
    asm("{ .reg .u64 t; cvta.to.shared.u64 t, %1; cvt.u32.u64 %0, t; }"
        : "=r"(a) : "l"(p));
    return a;
}

__device__ __forceinline__ void cpa16(uint32_t s, const void* g) {
    asm volatile("cp.async.ca.shared.global [%0], [%1], 16;" :: "r"(s), "l"(g));
}
#define CP_COMMIT() asm volatile("cp.async.commit_group;" ::: "memory")
#define CP_WAIT(n)  asm volatile("cp.async.wait_group %0;" :: "n"(n) : "memory")

__device__ __forceinline__ void ldsm_x4(uint32_t* r, uint32_t addr) {
    asm volatile("ldmatrix.sync.aligned.m8n8.x4.shared.b16 {%0,%1,%2,%3}, [%4];"
                 : "=r"(r[0]), "=r"(r[1]), "=r"(r[2]), "=r"(r[3]) : "r"(addr));
}
__device__ __forceinline__ void ldsm_x4_t(uint32_t* r, uint32_t addr) {
    asm volatile("ldmatrix.sync.aligned.m8n8.x4.trans.shared.b16 {%0,%1,%2,%3}, [%4];"
                 : "=r"(r[0]), "=r"(r[1]), "=r"(r[2]), "=r"(r[3]) : "r"(addr));
}

// fp16 MMA, fp32 accumulate
__device__ __forceinline__ void mma16816h(float* c, const uint32_t* a,
                                          const uint32_t* b) {
    asm volatile(
        "mma.sync.aligned.m16n8k16.row.col.f32.f16.f16.f32 "
        "{%0,%1,%2,%3}, {%4,%5,%6,%7}, {%8,%9}, {%0,%1,%2,%3};"
        : "+f"(c[0]), "+f"(c[1]), "+f"(c[2]), "+f"(c[3])
        : "r"(a[0]), "r"(a[1]), "r"(a[2]), "r"(a[3]), "r"(b[0]), "r"(b[1]));
}

__device__ __forceinline__ float ex2f(float x) {
    float y;
    asm("ex2.approx.ftz.f32 %0, %1;" : "=f"(y) : "f"(x));
    return y;
}

// pack two fp32 into f16x2 (lo = a, hi = b)
__device__ __forceinline__ uint32_t pack_h2(float a, float b) {
    uint32_t r;
    asm("cvt.rn.f16x2.f32 %0, %1, %2;" : "=r"(r) : "f"(b), "f"(a));
    return r;
}

// swizzled byte offset: 128B rows, SW128 (bits[6:4] ^= row&7)
#define ASW(row, colb) \
    ((uint32_t)(((row) << 7) + ((colb) ^ ((((uint32_t)(row)) & 7u) << 4))))

// ---------------------------------------------------------------------------
// Fused fp32 -> fp16 convert of all five inputs + counter reset (one launch)
// ---------------------------------------------------------------------------
#define NA8 ((BB * SQ * DD) / 8)   // 1048576
#define NW8 ((DD * DD) / 8)        // 131072
#define NCONV8 (2 * NA8 + 3 * NW8) // 2490368

__global__ void convall_kernel(const float* __restrict__ hs,
                               const float* __restrict__ ehs,
                               const float* __restrict__ Wq,
                               const float* __restrict__ Wk,
                               const float* __restrict__ Wv) {
    if (blockIdx.x == 0 && threadIdx.x < 12) g_cnt[threadIdx.x] = 0;
    int i = blockIdx.x * blockDim.x + threadIdx.x;
    if (i >= NCONV8) return;
    const float* src;
    __half* dst;
    int j = i;
    if (j < NA8) {
        src = hs;  dst = g_xh;
    } else if ((j -= NA8) < NA8) {
        src = ehs; dst = g_eh;
    } else if ((j -= NA8) < NW8) {
        src = Wq;  dst = g_wq;
    } else if ((j -= NW8) < NW8) {
        src = Wk;  dst = g_wk;
    } else {
        j -= NW8;
        src = Wv;  dst = g_wv;
    }
    float4 v0 = ((const float4*)src)[j * 2 + 0];
    float4 v1 = ((const float4*)src)[j * 2 + 1];
    uint4 o;
    o.x = pack_h2(v0.x, v0.y);
    o.y = pack_h2(v0.z, v0.w);
    o.z = pack_h2(v1.x, v1.y);
    o.w = pack_h2(v1.z, v1.w);
    ((uint4*)dst)[j] = o;
}

// ---------------------------------------------------------------------------
// Fused proj+attn kernel. bid < 1536: projection job (b-major: b, which, m, n);
// bid >= 1536: attention job (b-major: b, h, q-block), spins on g_cnt[.][b].
// In-bid-order dispatch => all proj blocks dispatched before any attn block.
// ---------------------------------------------------------------------------
#define PARR 10240u     // proj: bytes per smem array (128 rows * 80B stride)
#define PBUF 20480u     // proj: bytes per buffer (2 arrays: X, W)
#define QARR 16384u     // attn: 128 rows * 128B
#define KARR 8192u      // attn: 64 rows * 128B
#define KVBUF 16384u    // attn: 2 arrays (K, V) per slot
#define NPROJ 1536
#define FUSED_SMEM 65536

__device__ __forceinline__ void proj_body(int job) {
    extern __shared__ char smc[];
    const uint32_t smb = smem_u32(smc);
    const int tid = threadIdx.x;
    const int wid = tid >> 5, lane = tid & 31;
    const int gid = lane >> 2, tig = lane & 3;
    const int wm = wid & 1, wn = wid >> 1;

    // decode: b-major, then which, then 16 m-blocks x 8 n-blocks
    const int b = job / 384;
    int r = job - b * 384;
    const int which = r >> 7;          // / 128
    r &= 127;
    const int m0 = (b * 16 + (r >> 3)) * 128;
    const int n0 = (r & 7) * 128;

    const __half* x = (which == 0) ? g_xh : g_eh;
    const __half* w = (which == 0) ? g_wq : (which == 1) ? g_wk : g_wv;

    float acc[4][4][4];
#pragma unroll
    for (int a = 0; a < 4; a++)
#pragma unroll
        for (int bq = 0; bq < 4; bq++)
#pragma unroll
            for (int c = 0; c < 4; c++) acc[a][bq][c] = 0.0f;

    auto load_tile = [&](int kc, int p) {
        const int k0 = kc * 32;
        const uint32_t base = smb + (uint32_t)p * PBUF;
#pragma unroll
        for (int i = 0; i < 4; i++) {
            int c = tid + i * 256;
            int arr = c >> 9;
            int row = (c >> 2) & 127;
            int seg = c & 3;
            const __half* g = arr ? (w + (size_t)(n0 + row) * DD + k0 + seg * 8)
                                  : (x + (size_t)(m0 + row) * DD + k0 + seg * 8);
            cpa16(base + arr * PARR + row * 80 + seg * 16, g);
        }
        CP_COMMIT();
    };

    const int rowA = lane & 15, colA = (lane >> 4) * 8;
    const int rowB = (lane & 7) + ((lane >> 4) << 3);
    const int colB = ((lane >> 3) & 1) * 8;

    load_tile(0, 0);
    load_tile(1, 1);
    for (int t = 0; t < 32; t++) {
        if (t + 1 < 32) {
            CP_WAIT(1);
        } else {
            CP_WAIT(0);
        }
        __syncthreads();
        if (t + 2 < 32) load_tile(t + 2, (t + 2) % 3);

        const uint32_t bbase = smb + (uint32_t)(t % 3) * PBUF;
        const uint32_t X_s = bbase;
        const uint32_t W_s = bbase + PARR;

#pragma unroll
        for (int ks = 0; ks < 2; ks++) {
            const int k0s = ks * 16;
            uint32_t bw[2][4];
#pragma unroll
            for (int np = 0; np < 2; np++) {
                uint32_t ad = (wn * 32 + np * 16 + rowB) * 80 + (k0s + colB) * 2;
                ldsm_x4(bw[np], W_s + ad);
            }
#pragma unroll
            for (int mt = 0; mt < 4; mt++) {
                uint32_t ah[4];
                uint32_t ad = (wm * 64 + mt * 16 + rowA) * 80 + (k0s + colA) * 2;
                ldsm_x4(ah, X_s + ad);
#pragma unroll
                for (int nt = 0; nt < 4; nt++) {
                    const uint32_t* bp = &bw[nt >> 1][(nt & 1) * 2];
                    mma16816h(acc[mt][nt], ah, bp);
                }
            }
        }
    }

    // epilogue: fp16 write into head layout
    __half* dh = (which == 0) ? g_qh : (which == 1) ? g_kh : g_vh;
    const float qs = (which == 0) ? (0.125f * 1.4426950408889634f) : 1.0f;

#pragma unroll
    for (int mt = 0; mt < 4; mt++) {
        int m = m0 + wm * 64 + mt * 16 + gid;
        int bb = m >> 11;
        int s = m & (SQ - 1);
#pragma unroll
        for (int nt = 0; nt < 4; nt++) {
            int n = n0 + wn * 32 + nt * 8 + 2 * tig;
            int head = n >> 6;
            int hd = n & 63;
            size_t idx = (((size_t)bb * HH + head) * SQ + s) * HDIM + hd;
            *(uint32_t*)(dh + idx) =
                pack_h2(acc[mt][nt][0] * qs, acc[mt][nt][1] * qs);
            *(uint32_t*)(dh + idx + 8 * HDIM) =
                pack_h2(acc[mt][nt][2] * qs, acc[mt][nt][3] * qs);
        }
    }

    // signal completion: all stores visible, then one atomic per CTA
    __threadfence();
    __syncthreads();
    if (tid == 0) atomicAdd(&g_cnt[which * 4 + b], 1);
}

__device__ __forceinline__ void attn_body(int job, float* __restrict__ out) {
    extern __shared__ char smc[];
    const uint32_t smb = smem_u32(smc);
    const int tid = threadIdx.x;
    const int wid = tid >> 5, lane = tid & 31;
    const int gid = lane >> 2, tig = lane & 3;

    // decode: b-major, then h, then q-block
    const int b = job >> 8;            // / 256
    int r = job & 255;
    const int h = r >> 4;
    const int q0 = (r & 15) * 128;

    // wait for this batch's Q, K, V projections (128 CTAs each)
    if (tid == 0) {
        while (atomicAdd(&g_cnt[0 * 4 + b], 0) < 128) __nanosleep(64);
        while (atomicAdd(&g_cnt[1 * 4 + b], 0) < 128) __nanosleep(64);
        while (atomicAdd(&g_cnt[2 * 4 + b], 0) < 128) __nanosleep(64);
        __threadfence();
    }
    __syncthreads();
    __threadfence();

    const size_t bh = (size_t)b * HH + h;
    const __half* Qh_g = g_qh + (bh * SQ + q0) * HDIM;
    const __half* Kh_g = g_kh + bh * SK * HDIM;
    const __half* Vh_g = g_vh + bh * SK * HDIM;

    const uint32_t QH = smb;
    const uint32_t KV = smb + QARR;   // 3 slots

#pragma unroll
    for (int i = 0; i < 4; i++) {
        int c = tid + i * 256;
        int row = (c >> 3) & 127;
        int seg = c & 7;
        cpa16(QH + ASW(row, seg * 16), Qh_g + row * HDIM + seg * 8);
    }
    CP_COMMIT();

    auto load_kv = [&](int kt, int p) {
        const uint32_t base = KV + (uint32_t)p * KVBUF;
        const int key0 = kt * 64;
#pragma unroll
        for (int i = 0; i < 4; i++) {
            int c = tid + i * 256;
            int arr = c >> 9;
            int row = (c >> 3) & 63;
            int seg = c & 7;
            const __half* g =
                (arr ? Vh_g : Kh_g) + (size_t)(key0 + row) * HDIM + seg * 8;
            cpa16(base + arr * KARR + ASW(row, seg * 16), g);
        }
        CP_COMMIT();
    };

    load_kv(0, 0);
    load_kv(1, 1);
    CP_WAIT(2);   // Q group complete; kv0/kv1 may be in flight
    __syncthreads();

    const int rowA = lane & 15;
    const int colAb = (lane >> 4) * 16;
    uint32_t qh[4][4];
#pragma unroll
    for (int kk = 0; kk < 4; kk++)
        ldsm_x4(qh[kk], QH + ASW(wid * 16 + rowA, kk * 32 + colAb));

    float ctx[8][4];
#pragma unroll
    for (int t = 0; t < 8; t++)
#pragma unroll
        for (int c = 0; c < 4; c++) ctx[t][c] = 0.0f;
    float m_a = -1e30f, m_b = -1e30f, l_a = 0.0f, l_b = 0.0f;

    const int rowB = (lane & 7) + ((lane >> 4) << 3);
    const int colBb = ((lane >> 3) & 1) * 16;
    const int rowV = (lane & 7) + (((lane >> 3) & 1) << 3);
    const int colVb = (lane >> 4) * 16;

    const int NT = SK / 64;
    for (int t = 0; t < NT; t++) {
        if (t + 1 < NT) {
            CP_WAIT(1);
        } else {
            CP_WAIT(0);
        }
        __syncthreads();
        if (t + 2 < NT) load_kv(t + 2, (t + 2) % 3);

        const uint32_t kb = KV + (uint32_t)(t % 3) * KVBUF;
        const uint32_t KHs = kb, VHs = kb + KARR;

        float s[8][4];
#pragma unroll
        for (int tt = 0; tt < 8; tt++)
#pragma unroll
            for (int c = 0; c < 4; c++) s[tt][c] = 0.0f;

#pragma unroll
        for (int kk = 0; kk < 4; kk++) {
#pragma unroll
            for (int nn = 0; nn < 4; nn++) {
                uint32_t kh4[4];
                ldsm_x4(kh4, KHs + ASW(nn * 16 + rowB, kk * 32 + colBb));
                mma16816h(s[2 * nn], qh[kk], kh4);
                mma16816h(s[2 * nn + 1], qh[kk], kh4 + 2);
            }
        }

        float mA = s[0][0], mB = s[0][2];
#pragma unroll
        for (int tt = 0; tt < 8; tt++) {
            mA = fmaxf(mA, fmaxf(s[tt][0], s[tt][1]));
            mB = fmaxf(mB, fmaxf(s[tt][2], s[tt][3]));
        }
        mA = fmaxf(mA, __shfl_xor_sync(0xffffffffu, mA, 1));
        mA = fmaxf(mA, __shfl_xor_sync(0xffffffffu, mA, 2));
        mB = fmaxf(mB, __shfl_xor_sync(0xffffffffu, mB, 1));
        mB = fmaxf(mB, __shfl_xor_sync(0xffffffffu, mB, 2));
        float nmA = fmaxf(m_a, mA), nmB = fmaxf(m_b, mB);
        float corrA = ex2f(m_a - nmA), corrB = ex2f(m_b - nmB);

        float rA = 0.0f, rB = 0.0f;
#pragma unroll
        for (int tt = 0; tt < 8; tt++) {
            s[tt][0] = ex2f(s[tt][0] - nmA);
            s[tt][1] = ex2f(s[tt][1] - nmA);
            s[tt][2] = ex2f(s[tt][2] - nmB);
            s[tt][3] = ex2f(s[tt][3] - nmB);
            rA += s[tt][0] + s[tt][1];
            rB += s[tt][2] + s[tt][3];
        }
        l_a = l_a * corrA + rA;   // per-lane partial; corr is quad-uniform
        l_b = l_b * corrB + rB;
        m_a = nmA;
        m_b = nmB;
#pragma unroll
        for (int tt = 0; tt < 8; tt++) {
            ctx[tt][0] *= corrA;
            ctx[tt][1] *= corrA;
            ctx[tt][2] *= corrB;
            ctx[tt][3] *= corrB;
        }

#pragma unroll
        for (int j = 0; j < 4; j++) {
            uint32_t ah[4];
            ah[0] = pack_h2(s[2 * j][0], s[2 * j][1]);
            ah[1] = pack_h2(s[2 * j][2], s[2 * j][3]);
            ah[2] = pack_h2(s[2 * j + 1][0], s[2 * j + 1][1]);
            ah[3] = pack_h2(s[2 * j + 1][2], s[2 * j + 1][3]);
#pragma unroll
            for (int hp = 0; hp < 4; hp++) {
                uint32_t vh4[4];
                ldsm_x4_t(vh4, VHs + ASW(j * 16 + rowV, hp * 32 + colVb));
                mma16816h(ctx[2 * hp], ah, vh4);
                mma16816h(ctx[2 * hp + 1], ah, vh4 + 2);
            }
        }
    }

    l_a += __shfl_xor_sync(0xffffffffu, l_a, 1);
    l_a += __shfl_xor_sync(0xffffffffu, l_a, 2);
    l_b += __shfl_xor_sync(0xffffffffu, l_b, 1);
    l_b += __shfl_xor_sync(0xffffffffu, l_b, 2);

    float invA = 1.0f / l_a, invB = 1.0f / l_b;
    int qA = q0 + wid * 16 + gid;
    float* oA = out + ((size_t)b * SQ + qA) * DD + h * HDIM;
    float* oB = oA + (size_t)8 * DD;
#pragma unroll
    for (int tt = 0; tt < 8; tt++) {
        int hd = 8 * tt + 2 * tig;
        float2 a2 = make_float2(ctx[tt][0] * invA, ctx[tt][1] * invA);
        float2 b2 = make_float2(ctx[tt][2] * invB, ctx[tt][3] * invB);
        *(float2*)(oA + hd) = a2;
        *(float2*)(oB + hd) = b2;
    }
}

__global__ __launch_bounds__(256, 2) void fused_tc(float* __restrict__ out) {
    const int bid = blockIdx.x;
    if (bid < NPROJ) {
        proj_body(bid);
    } else {
        attn_body(bid - NPROJ, out);
    }
}

// ---------------------------------------------------------------------------
extern "C" void kernel_launch(void* const* d_in, const int* in_sizes, int n_in,
                              void* d_out, int out_size) {
    const float* hs = (const float*)d_in[0];
    const float* ehs = (const float*)d_in[1];
    const float* Wq = (const float*)d_in[2];
    const float* Wk = (const float*)d_in[3];
    const float* Wv = (const float*)d_in[4];
    float* out = (float*)d_out;

    // convert + counter reset
    convall_kernel<<<(NCONV8 + 255) / 256, 256>>>(hs, ehs, Wq, Wk, Wv);

    // fused proj+attn grid: 1536 proj blocks then 1024 attn blocks
    cudaFuncSetAttribute(fused_tc, cudaFuncAttributeMaxDynamicSharedMemorySize,
                         FUSED_SMEM);
    fused_tc<<<NPROJ + BB * HH * (SQ / 128), 256, FUSED_SMEM>>>(out);
}